// round 13
// baseline (speedup 1.0000x reference)
#include <cuda_runtime.h>

#define NB   8
#define TENC 512
#define DIN  512
#define TDEC 150
#define OD   80
#define DR   1024
#define PREN 256
#define AT   128
#define LOCC 32
#define KF   31

// ---------------- device scratch (16B-aligned: float4 access) ----------------
__device__ __align__(16) float g_pm[NB*TENC*AT];       // proc_mem [b,t,a]
__device__ __align__(16) float g_G[AT*KF];             // fused loc filters
__device__ __align__(16) float g_prev[TDEC*NB*OD];     // teacher-forced prev outputs
__device__ __align__(16) float g_p1[TDEC*NB*PREN];
__device__ __align__(16) float g_p2[TDEC*NB*PREN];
__device__ __align__(16) float g_h0[2*NB*DR];          // ping-pong state
__device__ __align__(16) float g_c0[2*NB*DR];
__device__ __align__(16) float g_h1[2*NB*DR];
__device__ __align__(16) float g_c1[2*NB*DR];
__device__ __align__(16) float g_cum[NB*TENC];
__device__ __align__(16) float g_q[NB*AT];             // q + attn_b for current step
__device__ __align__(16) float g_e[NB*TENC];
__device__ __align__(16) float g_w[NB*TENC];
__device__ __align__(16) float g_attc[NB*DIN];

__device__ __forceinline__ float sigf(float x){ return 1.f/(1.f + expf(-x)); }
__device__ __forceinline__ float wredsum(float v){
    v += __shfl_xor_sync(0xffffffffu, v, 16);
    v += __shfl_xor_sync(0xffffffffu, v, 8);
    v += __shfl_xor_sync(0xffffffffu, v, 4);
    v += __shfl_xor_sync(0xffffffffu, v, 2);
    v += __shfl_xor_sync(0xffffffffu, v, 1);
    return v;
}
__device__ __forceinline__ float dot4(float4 a, float4 b){
    return a.x*b.x + a.y*b.y + a.z*b.z + a.w*b.w;
}

// ---------------- init ----------------
__global__ void k_init(const float* __restrict__ targets, const float* __restrict__ attn_b,
                       const float* __restrict__ W_loc, const float* __restrict__ filt){
    int i = blockIdx.x*blockDim.x + threadIdx.x;      // 16384 threads
    if (i < 2*NB*DR){ g_h0[i]=0.f; g_c0[i]=0.f; g_h1[i]=0.f; g_c1[i]=0.f; }
    if (i < NB*TENC) g_cum[i] = 0.f;
    if (i < NB*AT)   g_q[i]   = attn_b[i & (AT-1)];
    if (i < AT*KF){
        int a = i / KF, k = i - a*KF;
        float s = 0.f;
        #pragma unroll
        for (int c=0;c<LOCC;c++) s += W_loc[a*LOCC+c] * filt[c*KF+k];
        g_G[i] = s;
    }
    int tot = gridDim.x*blockDim.x;
    for (int p=i; p < TDEC*NB*OD; p += tot){
        int o = p % OD; int sb = p / OD; int b = sb % NB; int t = sb / NB;
        g_prev[p] = (t==0) ? 0.f : targets[(b*TDEC + (t-1))*OD + o];
    }
}

// ---------------- tiled GEMM: C[M,N] = A[M,K] * B[N,K]^T (+bias)(relu) ----------------
__global__ void __launch_bounds__(256) k_gemm(const float* __restrict__ A, int lda,
                const float* __restrict__ Bm, int ldb, float* __restrict__ C, int ldc,
                int M, int N, int K, const float* __restrict__ bias, int relu){
    __shared__ float As[64][17];
    __shared__ float Bs[64][17];
    int bm = blockIdx.x*64, bn = blockIdx.y*64;
    int tid = threadIdx.x;
    int tx = tid & 15, ty = tid >> 4;
    float acc[4][4];
    #pragma unroll
    for(int i=0;i<4;i++){ acc[i][0]=0.f; acc[i][1]=0.f; acc[i][2]=0.f; acc[i][3]=0.f; }
    for (int k0=0;k0<K;k0+=16){
        #pragma unroll
        for (int l=tid; l<1024; l+=256){
            int r = l >> 4, c = l & 15;
            int kk = k0 + c;
            int m = bm + r;
            As[r][c] = (m < M && kk < K) ? A[m*lda + kk] : 0.f;
            int n = bn + r;
            Bs[r][c] = (n < N && kk < K) ? Bm[n*ldb + kk] : 0.f;
        }
        __syncthreads();
        #pragma unroll
        for (int kk=0;kk<16;kk++){
            float a[4], bv[4];
            #pragma unroll
            for (int i=0;i<4;i++) a[i]  = As[ty*4+i][kk];
            #pragma unroll
            for (int j=0;j<4;j++) bv[j] = Bs[tx*4+j][kk];
            #pragma unroll
            for (int i=0;i<4;i++)
                #pragma unroll
                for (int j=0;j<4;j++) acc[i][j] += a[i]*bv[j];
        }
        __syncthreads();
    }
    #pragma unroll
    for (int i=0;i<4;i++){
        int m = bm + ty*4 + i;
        if (m >= M) continue;
        #pragma unroll
        for (int j=0;j<4;j++){
            int n = bn + tx*4 + j;
            if (n >= N) continue;
            float v = acc[i][j];
            if (bias) v += bias[n];
            if (relu) v = fmaxf(v, 0.f);
            C[m*ldc + n] = v;
        }
    }
}

// ---------------- attention energies ----------------
__global__ void __launch_bounds__(256) k_energy(const float* __restrict__ attn_v){
    int b = blockIdx.x >> 4, chunk = blockIdx.x & 15;
    int t0 = chunk * 32;
    __shared__ float cum_s[62];
    __shared__ float q_s[AT];
    __shared__ float v_s[AT];
    __shared__ float G_s[AT*KF];
    int tid = threadIdx.x;
    if (tid < 62){
        int tt = t0 - 15 + tid;
        cum_s[tid] = (tt >= 0 && tt < TENC) ? g_cum[b*TENC + tt] : 0.f;
    }
    if (tid < AT){ q_s[tid] = g_q[b*AT + tid]; v_s[tid] = attn_v[tid]; }
    for (int i = tid; i < AT*KF; i += 256) G_s[i] = g_G[i];
    __syncthreads();
    int warp = tid >> 5, lane = tid & 31;
    #pragma unroll
    for (int w = 0; w < 4; w++){
        int tt = warp + w*8;
        int t = t0 + tt;
        const float* pm = g_pm + (b*TENC + t)*AT;
        float part = 0.f;
        #pragma unroll
        for (int i=0;i<4;i++){
            int a = lane + 32*i;
            float loc = 0.f;
            #pragma unroll
            for (int k=0;k<KF;k++) loc += cum_s[tt + k] * G_s[a*KF + k];
            part += v_s[a] * tanhf(pm[a] + q_s[a] + loc);
        }
        part = wredsum(part);
        if (lane == 0) g_e[b*TENC + t] = part;
    }
}

// ---------------- masked softmax + cum update + att_w out ----------------
__global__ void __launch_bounds__(512) k_softmax(const int* __restrict__ memlen,
                                                 float* __restrict__ out, int t){
    __shared__ float red[512];
    int b = blockIdx.x;
    int i = threadIdx.x;
    int len = memlen[b];
    float ev = (i < len) ? g_e[b*TENC + i] : -1e30f;
    red[i] = ev;
    __syncthreads();
    for (int s=256; s>0; s>>=1){
        if (i < s) red[i] = fmaxf(red[i], red[i+s]);
        __syncthreads();
    }
    float m = red[0];
    __syncthreads();
    float ex = (i < len) ? expf(ev - m) : 0.f;
    red[i] = ex;
    __syncthreads();
    for (int s=256; s>0; s>>=1){
        if (i < s) red[i] += red[i+s];
        __syncthreads();
    }
    float w = ex / red[0];
    g_w[b*TENC + i] = w;
    g_cum[b*TENC + i] += w;
    out[TDEC*NB*OD + TDEC*NB + (b*TDEC + t)*TENC + i] = w;
}

// ---------------- att_c[b,d] = sum_t w[t]*memory[b,t,d] ----------------
__global__ void __launch_bounds__(128) k_attc(const float* __restrict__ mem){
    int b = blockIdx.x >> 2, dc = blockIdx.x & 3;
    __shared__ float ws[TENC];
    for (int i = threadIdx.x; i < TENC; i += 128) ws[i] = g_w[b*TENC + i];
    __syncthreads();
    int d = dc*128 + threadIdx.x;
    const float* mp = mem + (b*TENC)*DIN + d;
    float a0=0.f,a1=0.f,a2=0.f,a3=0.f;
    for (int tt=0; tt<TENC; tt+=4){
        a0 += ws[tt+0]*mp[(tt+0)*DIN];
        a1 += ws[tt+1]*mp[(tt+1)*DIN];
        a2 += ws[tt+2]*mp[(tt+2)*DIN];
        a3 += ws[tt+3]*mp[(tt+3)*DIN];
    }
    g_attc[b*DIN + d] = (a0+a1)+(a2+a3);
}

// ---------------- LSTM0: warp owns j; 4 gates x 8 batches; grid 128x256 ----------------
__global__ void __launch_bounds__(256) k_lstm0(const float* __restrict__ Wi0,
                       const float* __restrict__ Wh0, const float* __restrict__ bl0, int t){
    int tid = threadIdx.x;
    int warp = tid>>5, lane = tid&31;
    int j = blockIdx.x*8 + warp;                // j in [0,1024)
    int rb = t & 1, wb = rb ^ 1;
    const float* h0r = g_h0 + rb*NB*DR;
    float acc[32];
    #pragma unroll
    for (int c=0;c<32;c++) acc[c]=0.f;
    // input part: x = [att_c(512), p2(256)], Wi0 rows of width 768
    #pragma unroll
    for (int k0=0;k0<768;k0+=128){
        int k = k0 + lane*4;
        float4 w0 = *(const float4*)(Wi0 + (j       )*768 + k);
        float4 w1 = *(const float4*)(Wi0 + (j + 1024)*768 + k);
        float4 w2 = *(const float4*)(Wi0 + (j + 2048)*768 + k);
        float4 w3 = *(const float4*)(Wi0 + (j + 3072)*768 + k);
        #pragma unroll
        for (int b=0;b<8;b++){
            float4 x = (k < 512) ? *(const float4*)(g_attc + b*DIN + k)
                                 : *(const float4*)(g_p2 + (t*NB+b)*PREN + (k-512));
            acc[0*8+b] += dot4(w0,x);
            acc[1*8+b] += dot4(w1,x);
            acc[2*8+b] += dot4(w2,x);
            acc[3*8+b] += dot4(w3,x);
        }
    }
    // hidden part
    #pragma unroll
    for (int k0=0;k0<1024;k0+=128){
        int k = k0 + lane*4;
        float4 w0 = *(const float4*)(Wh0 + (j       )*1024 + k);
        float4 w1 = *(const float4*)(Wh0 + (j + 1024)*1024 + k);
        float4 w2 = *(const float4*)(Wh0 + (j + 2048)*1024 + k);
        float4 w3 = *(const float4*)(Wh0 + (j + 3072)*1024 + k);
        #pragma unroll
        for (int b=0;b<8;b++){
            float4 x = *(const float4*)(h0r + b*DR + k);
            acc[0*8+b] += dot4(w0,x);
            acc[1*8+b] += dot4(w1,x);
            acc[2*8+b] += dot4(w2,x);
            acc[3*8+b] += dot4(w3,x);
        }
    }
    float myg = 0.f;
    #pragma unroll
    for (int c=0;c<32;c++){
        float v = wredsum(acc[c]);
        if (lane == c) myg = v;
    }
    int gg = lane>>3;
    myg += bl0[gg*1024 + j];
    float fv = __shfl_sync(0xffffffffu, myg, lane+8);
    float gv = __shfl_sync(0xffffffffu, myg, lane+16);
    float ov = __shfl_sync(0xffffffffu, myg, lane+24);
    if (lane < 8){
        int b = lane;
        float hold = h0r[b*DR + j];
        float cold = g_c0[rb*NB*DR + b*DR + j];
        float cn = sigf(fv)*cold + sigf(myg)*tanhf(gv);
        float hn = sigf(ov)*tanhf(cn);
        g_h0[wb*NB*DR + b*DR + j] = 0.9f*hn + 0.1f*hold;
        g_c0[wb*NB*DR + b*DR + j] = 0.9f*cn + 0.1f*cold;
    }
}

// ---------------- LSTM1: grid 128x256 ----------------
__global__ void __launch_bounds__(256) k_lstm1(const float* __restrict__ Wi1,
                       const float* __restrict__ Wh1, const float* __restrict__ bl1, int t){
    int tid = threadIdx.x;
    int warp = tid>>5, lane = tid&31;
    int j = blockIdx.x*8 + warp;                // j in [0,1024)
    int rb = t & 1, wb = rb ^ 1;
    const float* h0n = g_h0 + wb*NB*DR;     // freshly written by lstm0
    const float* h1r = g_h1 + rb*NB*DR;
    float acc[32];
    #pragma unroll
    for (int c=0;c<32;c++) acc[c]=0.f;
    #pragma unroll
    for (int k0=0;k0<1024;k0+=128){
        int k = k0 + lane*4;
        float4 w0 = *(const float4*)(Wi1 + (j       )*1024 + k);
        float4 w1 = *(const float4*)(Wi1 + (j + 1024)*1024 + k);
        float4 w2 = *(const float4*)(Wi1 + (j + 2048)*1024 + k);
        float4 w3 = *(const float4*)(Wi1 + (j + 3072)*1024 + k);
        #pragma unroll
        for (int b=0;b<8;b++){
            float4 x = *(const float4*)(h0n + b*DR + k);
            acc[0*8+b] += dot4(w0,x);
            acc[1*8+b] += dot4(w1,x);
            acc[2*8+b] += dot4(w2,x);
            acc[3*8+b] += dot4(w3,x);
        }
    }
    #pragma unroll
    for (int k0=0;k0<1024;k0+=128){
        int k = k0 + lane*4;
        float4 w0 = *(const float4*)(Wh1 + (j       )*1024 + k);
        float4 w1 = *(const float4*)(Wh1 + (j + 1024)*1024 + k);
        float4 w2 = *(const float4*)(Wh1 + (j + 2048)*1024 + k);
        float4 w3 = *(const float4*)(Wh1 + (j + 3072)*1024 + k);
        #pragma unroll
        for (int b=0;b<8;b++){
            float4 x = *(const float4*)(h1r + b*DR + k);
            acc[0*8+b] += dot4(w0,x);
            acc[1*8+b] += dot4(w1,x);
            acc[2*8+b] += dot4(w2,x);
            acc[3*8+b] += dot4(w3,x);
        }
    }
    float myg = 0.f;
    #pragma unroll
    for (int c=0;c<32;c++){
        float v = wredsum(acc[c]);
        if (lane == c) myg = v;
    }
    int gg = lane>>3;
    myg += bl1[gg*1024 + j];
    float fv = __shfl_sync(0xffffffffu, myg, lane+8);
    float gv = __shfl_sync(0xffffffffu, myg, lane+16);
    float ov = __shfl_sync(0xffffffffu, myg, lane+24);
    if (lane < 8){
        int b = lane;
        float hold = h1r[b*DR + j];
        float cold = g_c1[rb*NB*DR + b*DR + j];
        float cn = sigf(fv)*cold + sigf(myg)*tanhf(gv);
        float hn = sigf(ov)*tanhf(cn);
        g_h1[wb*NB*DR + b*DR + j] = 0.9f*hn + 0.1f*hold;
        g_c1[wb*NB*DR + b*DR + j] = 0.9f*cn + 0.1f*cold;
    }
}

// ---------------- post: feat/stop projections + q for next step ----------------
__global__ void __launch_bounds__(256) k_post(const float* __restrict__ feat_W,
                const float* __restrict__ stop_W, const float* __restrict__ stop_b,
                const float* __restrict__ W_q, const float* __restrict__ attn_b,
                float* __restrict__ out, int t){
    int b = blockIdx.x / 7, blk = blockIdx.x % 7;
    int warp = threadIdx.x>>5, lane = threadIdx.x&31;
    int wb = (t & 1) ^ 1;
    const float* h1 = g_h1 + wb*NB*DR + b*DR;
    const float* h0 = g_h0 + wb*NB*DR + b*DR;
    const float* ac = g_attc + b*DIN;
    for (int task = blk*8 + warp; task < 209; task += 56){
        float s = 0.f;
        if (task <= 80){
            const float* wrow = (task < 80) ? (feat_W + task*(DR+DIN)) : stop_W;
            for (int k = lane*4; k < DR; k += 128)
                s += dot4(*(const float4*)(wrow + k), *(const float4*)(h1 + k));
            for (int k = lane*4; k < DIN; k += 128)
                s += dot4(*(const float4*)(wrow + DR + k), *(const float4*)(ac + k));
            s = wredsum(s);
            if (lane == 0){
                if (task < 80) out[(b*TDEC + t)*OD + task] = s;
                else           out[TDEC*NB*OD + b*TDEC + t] = s + stop_b[0];
            }
        } else {
            int a = task - 81;
            const float* wrow = W_q + a*DR;
            for (int k = lane*4; k < DR; k += 128)
                s += dot4(*(const float4*)(wrow + k), *(const float4*)(h0 + k));
            s = wredsum(s);
            if (lane == 0) g_q[b*AT + a] = s + attn_b[a];
        }
    }
}

// ---------------- host launch ----------------
extern "C" void kernel_launch(void* const* d_in, const int* in_sizes, int n_in,
                              void* d_out, int out_size) {
    const float* memory  = (const float*)d_in[0];
    const int*   memlen  = (const int*)  d_in[1];
    const float* targets = (const float*)d_in[2];
    const float* W_mem   = (const float*)d_in[3];
    const float* W_q     = (const float*)d_in[4];
    const float* W_loc   = (const float*)d_in[5];
    const float* filt    = (const float*)d_in[6];
    const float* attn_v  = (const float*)d_in[7];
    const float* attn_b  = (const float*)d_in[8];
    const float* pre_W1  = (const float*)d_in[9];
    const float* pre_b1  = (const float*)d_in[10];
    const float* pre_W2  = (const float*)d_in[11];
    const float* pre_b2  = (const float*)d_in[12];
    const float* Wi0     = (const float*)d_in[13];
    const float* Wh0     = (const float*)d_in[14];
    const float* bl0     = (const float*)d_in[15];
    const float* Wi1     = (const float*)d_in[16];
    const float* Wh1     = (const float*)d_in[17];
    const float* bl1     = (const float*)d_in[18];
    const float* feat_W  = (const float*)d_in[19];
    const float* stop_W  = (const float*)d_in[20];
    const float* stop_b  = (const float*)d_in[21];
    float* out = (float*)d_out;

    // CRITICAL (GB300/ATS): taking the address of a __device__ symbol in HOST
    // code yields the host shadow, which the GPU can silently access via ATS.
    // Resolve real device addresses before passing them as kernel args.
    float *pm_d = nullptr, *prev_d = nullptr, *p1_d = nullptr, *p2_d = nullptr;
    cudaGetSymbolAddress((void**)&pm_d,   g_pm);
    cudaGetSymbolAddress((void**)&prev_d, g_prev);
    cudaGetSymbolAddress((void**)&p1_d,   g_p1);
    cudaGetSymbolAddress((void**)&p2_d,   g_p2);

    k_init<<<64, 256>>>(targets, attn_b, W_loc, filt);
    // proc_mem = memory @ W_mem^T : [4096,128]
    k_gemm<<<dim3(64,2), 256>>>(memory, DIN, W_mem, DIN, pm_d, AT, NB*TENC, AT, DIN, nullptr, 0);
    // prenet (all steps at once, M = 1200)
    k_gemm<<<dim3(19,4), 256>>>(prev_d, OD,   pre_W1, OD,   p1_d, PREN, TDEC*NB, PREN, OD,   pre_b1, 1);
    k_gemm<<<dim3(19,4), 256>>>(p1_d,   PREN, pre_W2, PREN, p2_d, PREN, TDEC*NB, PREN, PREN, pre_b2, 1);

    for (int t = 0; t < TDEC; t++){
        k_energy <<<128, 256>>>(attn_v);
        k_softmax<<<NB, 512>>>(memlen, out, t);
        k_attc   <<<32, 128>>>(memory);
        k_lstm0  <<<128, 256>>>(Wi0, Wh0, bl0, t);
        k_lstm1  <<<128, 256>>>(Wi1, Wh1, bl1, t);
        k_post   <<<56, 256>>>(feat_W, stop_W, stop_b, W_q, attn_b, out, t);
    }
}

// round 14
// speedup vs baseline: 1.5611x; 1.5611x over previous
#include <cuda_runtime.h>

#define NB   8
#define TENC 512
#define DIN  512
#define TDEC 150
#define OD   80
#define DR   1024
#define PREN 256
#define AT   128
#define LOCC 32
#define KF   31
#define GRID 148

// ---------------- device scratch (16B-aligned: float4 access) ----------------
__device__ __align__(16) float g_pm[NB*TENC*AT];       // proc_mem [b,t,a]
__device__ __align__(16) float g_G[AT*KF];             // fused loc filters
__device__ __align__(16) float g_prev[TDEC*NB*OD];     // teacher-forced prev outputs
__device__ __align__(16) float g_p1[TDEC*NB*PREN];
__device__ __align__(16) float g_p2[TDEC*NB*PREN];
__device__ __align__(16) float g_h0[2*NB*DR];          // ping-pong state
__device__ __align__(16) float g_c0[2*NB*DR];
__device__ __align__(16) float g_h1[2*NB*DR];
__device__ __align__(16) float g_c1[2*NB*DR];
__device__ __align__(16) float g_cum[NB*TENC];
__device__ __align__(16) float g_q[NB*AT];
__device__ __align__(16) float g_e[NB*TENC];
__device__ __align__(16) float g_w[NB*TENC];
__device__ __align__(16) float g_attc[NB*DIN];
__device__ unsigned g_bar_count;
__device__ unsigned g_bar_sense;

__device__ __forceinline__ float sigf(float x){ return 1.f/(1.f + expf(-x)); }
__device__ __forceinline__ float wredsum(float v){
    v += __shfl_xor_sync(0xffffffffu, v, 16);
    v += __shfl_xor_sync(0xffffffffu, v, 8);
    v += __shfl_xor_sync(0xffffffffu, v, 4);
    v += __shfl_xor_sync(0xffffffffu, v, 2);
    v += __shfl_xor_sync(0xffffffffu, v, 1);
    return v;
}
__device__ __forceinline__ float dot4(float4 a, float4 b){
    return a.x*b.x + a.y*b.y + a.z*b.z + a.w*b.w;
}
// packed fp32x2 FMA (FFMA2): exact fp32, 2 MACs/instr (PTX-only per SASS_QUICKREF)
__device__ __forceinline__ void ffma2(unsigned long long &d, unsigned long long a, unsigned long long b){
    asm("fma.rn.f32x2 %0, %1, %2, %0;" : "+l"(d) : "l"(a), "l"(b));
}
__device__ __forceinline__ float pairsum(unsigned long long v){
    float lo = __uint_as_float((unsigned)(v & 0xffffffffull));
    float hi = __uint_as_float((unsigned)(v >> 32));
    return lo + hi;
}
struct U2 { unsigned long long a, b; };
__device__ __forceinline__ U2 ldu2(const float* p){
    union { float4 f; U2 u; } t;
    t.f = *(const float4*)p;
    return t.u;
}
__device__ __forceinline__ float tanha(float x){
    float y; asm("tanh.approx.f32 %0, %1;" : "=f"(y) : "f"(x)); return y;
}

// grid barrier: sense-reversing; __threadfence() (gpu scope) emits CCTL.IVALL
// which invalidates this SM's L1D -> fresh cross-block data after each phase.
__device__ __forceinline__ void gridbar(){
    __syncthreads();
    if (threadIdx.x == 0){
        volatile unsigned* sense = &g_bar_sense;
        unsigned s = *sense;
        __threadfence();
        if (atomicAdd(&g_bar_count, 1u) == (unsigned)(GRID-1)){
            g_bar_count = 0u;
            __threadfence();
            *sense = s ^ 1u;
        } else {
            while (*sense == s) {}
            __threadfence();
        }
    }
    __syncthreads();
}

// ---------------- init ----------------
__global__ void k_init(const float* __restrict__ targets, const float* __restrict__ attn_b,
                       const float* __restrict__ W_loc, const float* __restrict__ filt){
    int i = blockIdx.x*blockDim.x + threadIdx.x;
    if (i == 0){ g_bar_count = 0u; g_bar_sense = 0u; }
    if (i < 2*NB*DR){ g_h0[i]=0.f; g_c0[i]=0.f; g_h1[i]=0.f; g_c1[i]=0.f; }
    if (i < NB*TENC) g_cum[i] = 0.f;
    if (i < NB*AT)   g_q[i]   = attn_b[i & (AT-1)];
    if (i < AT*KF){
        int a = i / KF, k = i - a*KF;
        float s = 0.f;
        #pragma unroll
        for (int c=0;c<LOCC;c++) s += W_loc[a*LOCC+c] * filt[c*KF+k];
        g_G[i] = s;
    }
    int tot = gridDim.x*blockDim.x;
    for (int p=i; p < TDEC*NB*OD; p += tot){
        int o = p % OD; int sb = p / OD; int b = sb % NB; int t = sb / NB;
        g_prev[p] = (t==0) ? 0.f : targets[(b*TDEC + (t-1))*OD + o];
    }
}

// ---------------- tiled GEMM: C[M,N] = A[M,K] * B[N,K]^T (+bias)(relu) ----------------
__global__ void __launch_bounds__(256) k_gemm(const float* __restrict__ A, int lda,
                const float* __restrict__ Bm, int ldb, float* __restrict__ C, int ldc,
                int M, int N, int K, const float* __restrict__ bias, int relu){
    __shared__ float As[64][17];
    __shared__ float Bs[64][17];
    int bm = blockIdx.x*64, bn = blockIdx.y*64;
    int tid = threadIdx.x;
    int tx = tid & 15, ty = tid >> 4;
    float acc[4][4];
    #pragma unroll
    for(int i=0;i<4;i++){ acc[i][0]=0.f; acc[i][1]=0.f; acc[i][2]=0.f; acc[i][3]=0.f; }
    for (int k0=0;k0<K;k0+=16){
        #pragma unroll
        for (int l=tid; l<1024; l+=256){
            int r = l >> 4, c = l & 15;
            int kk = k0 + c;
            int m = bm + r;
            As[r][c] = (m < M && kk < K) ? A[m*lda + kk] : 0.f;
            int n = bn + r;
            Bs[r][c] = (n < N && kk < K) ? Bm[n*ldb + kk] : 0.f;
        }
        __syncthreads();
        #pragma unroll
        for (int kk=0;kk<16;kk++){
            float a[4], bv[4];
            #pragma unroll
            for (int i=0;i<4;i++) a[i]  = As[ty*4+i][kk];
            #pragma unroll
            for (int j=0;j<4;j++) bv[j] = Bs[tx*4+j][kk];
            #pragma unroll
            for (int i=0;i<4;i++)
                #pragma unroll
                for (int j=0;j<4;j++) acc[i][j] += a[i]*bv[j];
        }
        __syncthreads();
    }
    #pragma unroll
    for (int i=0;i<4;i++){
        int m = bm + ty*4 + i;
        if (m >= M) continue;
        #pragma unroll
        for (int j=0;j<4;j++){
            int n = bn + tx*4 + j;
            if (n >= N) continue;
            float v = acc[i][j];
            if (bias) v += bias[n];
            if (relu) v = fmaxf(v, 0.f);
            C[m*ldc + n] = v;
        }
    }
}

// ---------------- persistent decoder: all 150 steps, 6 grid barriers/step ----------------
__global__ void __launch_bounds__(512, 1) k_decoder(
    const float* __restrict__ mem, const int* __restrict__ memlen,
    const float* __restrict__ attn_v,
    const float* __restrict__ Wi0, const float* __restrict__ Wh0, const float* __restrict__ bl0,
    const float* __restrict__ Wi1, const float* __restrict__ Wh1, const float* __restrict__ bl1,
    const float* __restrict__ feat_W, const float* __restrict__ stop_W, const float* __restrict__ stop_b,
    const float* __restrict__ W_q, const float* __restrict__ attn_b,
    float* __restrict__ out)
{
    __shared__ float G_s[AT*KF];
    __shared__ float v_s[AT];
    __shared__ float q_s[AT];
    __shared__ float cum_s[62];
    __shared__ float red[512];
    __shared__ float ws_s[64];
    __shared__ float sred[512];

    const int tid  = threadIdx.x;
    const int warp = tid >> 5, lane = tid & 31;
    const int blk  = blockIdx.x;

    for (int i = tid; i < AT*KF; i += 512) G_s[i] = g_G[i];
    if (tid < AT) v_s[tid] = attn_v[tid];
    __syncthreads();

    for (int t = 0; t < TDEC; t++){
        const int rb = t & 1, wb = rb ^ 1;

        // ---- P1: energies (blocks 0-127); block 128 zeroes attc ----
        if (blk < 128){
            int b = blk >> 4, chunk = blk & 15, t0 = chunk*32;
            if (tid < 62){
                int tg = t0 - 15 + tid;
                cum_s[tid] = (tg >= 0 && tg < TENC) ? g_cum[b*TENC + tg] : 0.f;
            }
            if (tid < AT) q_s[tid] = g_q[b*AT + tid];
            __syncthreads();
            for (int tt = warp; tt < 32; tt += 16){
                int tg = t0 + tt;
                const float* pm = g_pm + (b*TENC + tg)*AT;
                float part = 0.f;
                #pragma unroll
                for (int i=0;i<4;i++){
                    int a = lane + 32*i;
                    float loc = 0.f;
                    #pragma unroll
                    for (int k=0;k<KF;k++) loc += cum_s[tt+k]*G_s[a*KF+k];
                    part += v_s[a]*tanha(pm[a] + q_s[a] + loc);
                }
                part = wredsum(part);
                if (lane == 0) g_e[b*TENC + tg] = part;
            }
        } else if (blk == 128){
            for (int i = tid; i < NB*DIN; i += 512) g_attc[i] = 0.f;
        }
        gridbar();

        // ---- P2: masked softmax + cum + att_w output (blocks 0-7) ----
        if (blk < NB){
            int b = blk, i = tid;
            int len = memlen[b];
            float ev = (i < len) ? g_e[b*TENC + i] : -1e30f;
            red[i] = ev; __syncthreads();
            for (int s=256; s>0; s>>=1){ if (i < s) red[i] = fmaxf(red[i], red[i+s]); __syncthreads(); }
            float m = red[0]; __syncthreads();
            float ex = (i < len) ? expf(ev - m) : 0.f;
            red[i] = ex; __syncthreads();
            for (int s=256; s>0; s>>=1){ if (i < s) red[i] += red[i+s]; __syncthreads(); }
            float w = ex / red[0];
            g_w[b*TENC + i] = w;
            g_cum[b*TENC + i] += w;
            out[TDEC*NB*OD + TDEC*NB + (b*TDEC + t)*TENC + i] = w;
        }
        gridbar();

        // ---- P3: att_c via 8-way t-split + atomics (blocks 0-63) ----
        if (blk < 64){
            int b = blk >> 3, tc = blk & 7;
            if (tid < 64) ws_s[tid] = g_w[b*TENC + tc*64 + tid];
            __syncthreads();
            const float* mp = mem + (b*TENC + tc*64)*DIN + tid;
            float a0=0.f,a1=0.f,a2=0.f,a3=0.f,a4=0.f,a5=0.f,a6=0.f,a7=0.f;
            #pragma unroll
            for (int i=0;i<64;i+=8){
                a0 += ws_s[i+0]*mp[(i+0)*DIN];
                a1 += ws_s[i+1]*mp[(i+1)*DIN];
                a2 += ws_s[i+2]*mp[(i+2)*DIN];
                a3 += ws_s[i+3]*mp[(i+3)*DIN];
                a4 += ws_s[i+4]*mp[(i+4)*DIN];
                a5 += ws_s[i+5]*mp[(i+5)*DIN];
                a6 += ws_s[i+6]*mp[(i+6)*DIN];
                a7 += ws_s[i+7]*mp[(i+7)*DIN];
            }
            atomicAdd(&g_attc[b*DIN + tid], ((a0+a1)+(a2+a3)) + ((a4+a5)+(a6+a7)));
        }
        gridbar();

        // ---- P4: LSTM0 (blocks 0-127; warp pair per j, k-split; FFMA2) ----
        if (blk < 128){
            int j = blk*8 + (warp>>1);
            int half = warp & 1;
            const float* h0r = g_h0 + rb*NB*DR;
            unsigned long long acc[32];
            #pragma unroll
            for (int c=0;c<32;c++) acc[c] = 0ull;
            #pragma unroll
            for (int c=0;c<3;c++){                      // input x = [attc|p2], 768 wide
                int k = half*384 + c*128 + lane*4;
                U2 xv[8];
                #pragma unroll
                for (int b=0;b<8;b++)
                    xv[b] = (k < 512) ? ldu2(g_attc + b*DIN + k)
                                      : ldu2(g_p2 + (t*NB+b)*PREN + (k-512));
                #pragma unroll
                for (int g=0; g<4; g++){
                    U2 w = ldu2(Wi0 + (j + g*1024)*768 + k);
                    #pragma unroll
                    for (int b=0;b<8;b++){ ffma2(acc[g*8+b], w.a, xv[b].a); ffma2(acc[g*8+b], w.b, xv[b].b); }
                }
            }
            #pragma unroll
            for (int c=0;c<4;c++){                      // hidden, 1024 wide
                int k = half*512 + c*128 + lane*4;
                U2 xv[8];
                #pragma unroll
                for (int b=0;b<8;b++) xv[b] = ldu2(h0r + b*DR + k);
                #pragma unroll
                for (int g=0; g<4; g++){
                    U2 w = ldu2(Wh0 + (j + g*1024)*1024 + k);
                    #pragma unroll
                    for (int b=0;b<8;b++){ ffma2(acc[g*8+b], w.a, xv[b].a); ffma2(acc[g*8+b], w.b, xv[b].b); }
                }
            }
            float myg = 0.f;
            #pragma unroll
            for (int c=0;c<32;c++){
                float v = wredsum(pairsum(acc[c]));
                if (lane == c) myg = v;
            }
            sred[warp*32 + lane] = myg;
            __syncthreads();
            if (half == 0){
                myg += sred[(warp+1)*32 + lane];
                myg += bl0[(lane>>3)*1024 + j];
                float fv = __shfl_sync(0xffffffffu, myg, lane+8);
                float gv = __shfl_sync(0xffffffffu, myg, lane+16);
                float ov = __shfl_sync(0xffffffffu, myg, lane+24);
                if (lane < 8){
                    int b = lane;
                    float hold = h0r[b*DR + j];
                    float cold = g_c0[rb*NB*DR + b*DR + j];
                    float cn = sigf(fv)*cold + sigf(myg)*tanhf(gv);
                    float hn = sigf(ov)*tanhf(cn);
                    g_h0[wb*NB*DR + b*DR + j] = 0.9f*hn + 0.1f*hold;
                    g_c0[wb*NB*DR + b*DR + j] = 0.9f*cn + 0.1f*cold;
                }
            }
        }
        gridbar();

        // ---- P5: LSTM1 ----
        if (blk < 128){
            int j = blk*8 + (warp>>1);
            int half = warp & 1;
            const float* h0n = g_h0 + wb*NB*DR;
            const float* h1r = g_h1 + rb*NB*DR;
            unsigned long long acc[32];
            #pragma unroll
            for (int c=0;c<32;c++) acc[c] = 0ull;
            #pragma unroll
            for (int c=0;c<4;c++){
                int k = half*512 + c*128 + lane*4;
                U2 xv[8];
                #pragma unroll
                for (int b=0;b<8;b++) xv[b] = ldu2(h0n + b*DR + k);
                #pragma unroll
                for (int g=0; g<4; g++){
                    U2 w = ldu2(Wi1 + (j + g*1024)*1024 + k);
                    #pragma unroll
                    for (int b=0;b<8;b++){ ffma2(acc[g*8+b], w.a, xv[b].a); ffma2(acc[g*8+b], w.b, xv[b].b); }
                }
            }
            #pragma unroll
            for (int c=0;c<4;c++){
                int k = half*512 + c*128 + lane*4;
                U2 xv[8];
                #pragma unroll
                for (int b=0;b<8;b++) xv[b] = ldu2(h1r + b*DR + k);
                #pragma unroll
                for (int g=0; g<4; g++){
                    U2 w = ldu2(Wh1 + (j + g*1024)*1024 + k);
                    #pragma unroll
                    for (int b=0;b<8;b++){ ffma2(acc[g*8+b], w.a, xv[b].a); ffma2(acc[g*8+b], w.b, xv[b].b); }
                }
            }
            float myg = 0.f;
            #pragma unroll
            for (int c=0;c<32;c++){
                float v = wredsum(pairsum(acc[c]));
                if (lane == c) myg = v;
            }
            sred[warp*32 + lane] = myg;
            __syncthreads();
            if (half == 0){
                myg += sred[(warp+1)*32 + lane];
                myg += bl1[(lane>>3)*1024 + j];
                float fv = __shfl_sync(0xffffffffu, myg, lane+8);
                float gv = __shfl_sync(0xffffffffu, myg, lane+16);
                float ov = __shfl_sync(0xffffffffu, myg, lane+24);
                if (lane < 8){
                    int b = lane;
                    float hold = h1r[b*DR + j];
                    float cold = g_c1[rb*NB*DR + b*DR + j];
                    float cn = sigf(fv)*cold + sigf(myg)*tanhf(gv);
                    float hn = sigf(ov)*tanhf(cn);
                    g_h1[wb*NB*DR + b*DR + j] = 0.9f*hn + 0.1f*hold;
                    g_c1[wb*NB*DR + b*DR + j] = 0.9f*cn + 0.1f*cold;
                }
            }
        }
        gridbar();

        // ---- P6: feat/stop projections + q for next step (1672 warp-tasks) ----
        {
            int gw = blk*16 + warp;
            if (gw < 8*209){
                int b = gw / 209, task = gw % 209;
                const float* h1 = g_h1 + wb*NB*DR + b*DR;
                const float* h0 = g_h0 + wb*NB*DR + b*DR;
                const float* ac = g_attc + b*DIN;
                float s = 0.f;
                if (task <= 80){
                    const float* wrow = (task < 80) ? (feat_W + task*(DR+DIN)) : stop_W;
                    for (int k = lane*4; k < DR; k += 128)
                        s += dot4(*(const float4*)(wrow + k), *(const float4*)(h1 + k));
                    for (int k = lane*4; k < DIN; k += 128)
                        s += dot4(*(const float4*)(wrow + DR + k), *(const float4*)(ac + k));
                    s = wredsum(s);
                    if (lane == 0){
                        if (task < 80) out[(b*TDEC + t)*OD + task] = s;
                        else           out[TDEC*NB*OD + b*TDEC + t] = s + stop_b[0];
                    }
                } else {
                    int a = task - 81;
                    const float* wrow = W_q + a*DR;
                    for (int k = lane*4; k < DR; k += 128)
                        s += dot4(*(const float4*)(wrow + k), *(const float4*)(h0 + k));
                    s = wredsum(s);
                    if (lane == 0) g_q[b*AT + a] = s + attn_b[a];
                }
            }
        }
        gridbar();
    }
}

// ---------------- host launch ----------------
extern "C" void kernel_launch(void* const* d_in, const int* in_sizes, int n_in,
                              void* d_out, int out_size) {
    const float* memory  = (const float*)d_in[0];
    const int*   memlen  = (const int*)  d_in[1];
    const float* targets = (const float*)d_in[2];
    const float* W_mem   = (const float*)d_in[3];
    const float* W_q     = (const float*)d_in[4];
    const float* W_loc   = (const float*)d_in[5];
    const float* filt    = (const float*)d_in[6];
    const float* attn_v  = (const float*)d_in[7];
    const float* attn_b  = (const float*)d_in[8];
    const float* pre_W1  = (const float*)d_in[9];
    const float* pre_b1  = (const float*)d_in[10];
    const float* pre_W2  = (const float*)d_in[11];
    const float* pre_b2  = (const float*)d_in[12];
    const float* Wi0     = (const float*)d_in[13];
    const float* Wh0     = (const float*)d_in[14];
    const float* bl0     = (const float*)d_in[15];
    const float* Wi1     = (const float*)d_in[16];
    const float* Wh1     = (const float*)d_in[17];
    const float* bl1     = (const float*)d_in[18];
    const float* feat_W  = (const float*)d_in[19];
    const float* stop_W  = (const float*)d_in[20];
    const float* stop_b  = (const float*)d_in[21];
    float* out = (float*)d_out;

    // GB300/ATS: host-side &symbol is the host shadow; resolve device addresses.
    float *pm_d = nullptr, *prev_d = nullptr, *p1_d = nullptr, *p2_d = nullptr;
    cudaGetSymbolAddress((void**)&pm_d,   g_pm);
    cudaGetSymbolAddress((void**)&prev_d, g_prev);
    cudaGetSymbolAddress((void**)&p1_d,   g_p1);
    cudaGetSymbolAddress((void**)&p2_d,   g_p2);

    k_init<<<64, 256>>>(targets, attn_b, W_loc, filt);
    k_gemm<<<dim3(64,2), 256>>>(memory, DIN, W_mem, DIN, pm_d, AT, NB*TENC, AT, DIN, nullptr, 0);
    k_gemm<<<dim3(19,4), 256>>>(prev_d, OD,   pre_W1, OD,   p1_d, PREN, TDEC*NB, PREN, OD,   pre_b1, 1);
    k_gemm<<<dim3(19,4), 256>>>(p1_d,   PREN, pre_W2, PREN, p2_d, PREN, TDEC*NB, PREN, PREN, pre_b2, 1);

    k_decoder<<<GRID, 512>>>(memory, memlen, attn_v,
                             Wi0, Wh0, bl0, Wi1, Wh1, bl1,
                             feat_W, stop_W, stop_b, W_q, attn_b, out);
}